// round 4
// baseline (speedup 1.0000x reference)
#include <cuda_runtime.h>
#include <math.h>

#define B_ 4
#define V_ 50000
#define C_ 256
#define K_ 128
#define LAMBDA 100.0f
#define NCHUNK 19
#define TPC 165
#define NTILES 3125
#define LD 129
#define SOLVE_SMEM ((LD * LD + K_ + 32) * 4)

__device__ float g_part1[(size_t)NCHUNK * 8 * K_ * C_];
__device__ float g_A[8 * K_ * C_];
__device__ float g_AA2[2 * 2 * B_ * K_ * K_];

__global__ __launch_bounds__(256, 2)
void gemm1(const float* __restrict__ fx, const float* __restrict__ fy,
           const float* __restrict__ ex, const float* __restrict__ ey)
{
    const int chunk = blockIdx.x, ntile = blockIdx.y, p = blockIdx.z;
    const int b = p >> 1, which = p & 1;
    const float* E = (which ? ey : ex) + (size_t)b * K_ * V_;
    const float* F = (which ? fy : fx) + (size_t)b * V_ * C_ + ntile * 128;
    float* out = g_part1 + ((size_t)chunk * 8 + which * 4 + b) * K_ * C_ + ntile * 128;

    __shared__ float Es[16][132];
    __shared__ float Fs[16][128];

    const int tid = threadIdx.x;
    const int lk = tid >> 1, lq = tid & 1;
    const int fr = tid >> 5, fc = (tid & 31) << 2;
    const int tm = tid >> 4, tn = tid & 15;
    const float* Erow = E + (size_t)lk * V_;

    float acc[8][8];
#pragma unroll
    for (int i = 0; i < 8; ++i)
#pragma unroll
        for (int j = 0; j < 8; ++j) acc[i][j] = 0.0f;

    const int t0 = chunk * TPC;
    const int t1 = (t0 + TPC < NTILES) ? (t0 + TPC) : NTILES;

    for (int t = t0; t < t1; ++t) {
        const int v = t << 4;
        float4 e0 = *(const float4*)(Erow + v + (lq << 2));
        float4 e1 = *(const float4*)(Erow + v + (lq << 2) + 8);
        float4 f0 = *(const float4*)(F + (size_t)(v + fr) * C_ + fc);
        float4 f1 = *(const float4*)(F + (size_t)(v + fr + 8) * C_ + fc);
        __syncthreads();
        const int r0 = lq << 2;
        Es[r0 + 0][lk] = e0.x; Es[r0 + 1][lk] = e0.y;
        Es[r0 + 2][lk] = e0.z; Es[r0 + 3][lk] = e0.w;
        Es[r0 + 8][lk] = e1.x; Es[r0 + 9][lk] = e1.y;
        Es[r0 + 10][lk] = e1.z; Es[r0 + 11][lk] = e1.w;
        *(float4*)&Fs[fr][fc] = f0;
        *(float4*)&Fs[fr + 8][fc] = f1;
        __syncthreads();
#pragma unroll
        for (int vv = 0; vv < 16; ++vv) {
            float4 a0 = *(const float4*)&Es[vv][tm << 2];
            float4 a1 = *(const float4*)&Es[vv][64 + (tm << 2)];
            float4 b0 = *(const float4*)&Fs[vv][tn << 2];
            float4 b1 = *(const float4*)&Fs[vv][64 + (tn << 2)];
            float a[8] = {a0.x, a0.y, a0.z, a0.w, a1.x, a1.y, a1.z, a1.w};
            float bb[8] = {b0.x, b0.y, b0.z, b0.w, b1.x, b1.y, b1.z, b1.w};
#pragma unroll
            for (int i = 0; i < 8; ++i)
#pragma unroll
                for (int j = 0; j < 8; ++j) acc[i][j] += a[i] * bb[j];
        }
    }
#pragma unroll
    for (int i = 0; i < 8; ++i) {
        const int row = (i < 4) ? ((tm << 2) + i) : (64 + (tm << 2) + i - 4);
        float4 o0 = {acc[i][0], acc[i][1], acc[i][2], acc[i][3]};
        float4 o1 = {acc[i][4], acc[i][5], acc[i][6], acc[i][7]};
        *(float4*)(out + (size_t)row * C_ + (tn << 2)) = o0;
        *(float4*)(out + (size_t)row * C_ + 64 + (tn << 2)) = o1;
    }
}

__global__ void reduceA()
{
    const int i = blockIdx.x * 256 + threadIdx.x;
    float s = 0.0f;
#pragma unroll
    for (int c = 0; c < NCHUNK; ++c) s += g_part1[(size_t)c * 8 * K_ * C_ + i];
    g_A[i] = s;
}

__global__ __launch_bounds__(256, 2)
void gemm2()
{
    const int cc = blockIdx.x;
    const int t = blockIdx.y & 1, b = blockIdx.y >> 1;
    const float* P = g_A + ((size_t)(t * B_ + b) * K_) * C_ + cc * 128;
    const float* Q = g_A + ((size_t)b * K_) * C_ + cc * 128;
    float* out = g_AA2 + ((size_t)((cc * 2 + t) * B_ + b) * K_) * K_;

    __shared__ float Ps[16][132];
    __shared__ float Qs[16][132];
    const int tid = threadIdx.x;
    const int lk = tid >> 1, lq = tid & 1;
    const int tm = tid >> 4, tn = tid & 15;

    float acc[8][8];
#pragma unroll
    for (int i = 0; i < 8; ++i)
#pragma unroll
        for (int j = 0; j < 8; ++j) acc[i][j] = 0.0f;

    for (int kt = 0; kt < 8; ++kt) {
        const int c = kt << 4;
        float4 p0 = *(const float4*)(P + (size_t)lk * C_ + c + (lq << 2));
        float4 p1 = *(const float4*)(P + (size_t)lk * C_ + c + (lq << 2) + 8);
        float4 q0 = *(const float4*)(Q + (size_t)lk * C_ + c + (lq << 2));
        float4 q1 = *(const float4*)(Q + (size_t)lk * C_ + c + (lq << 2) + 8);
        __syncthreads();
        const int r0 = lq << 2;
        Ps[r0 + 0][lk] = p0.x; Ps[r0 + 1][lk] = p0.y; Ps[r0 + 2][lk] = p0.z; Ps[r0 + 3][lk] = p0.w;
        Ps[r0 + 8][lk] = p1.x; Ps[r0 + 9][lk] = p1.y; Ps[r0 + 10][lk] = p1.z; Ps[r0 + 11][lk] = p1.w;
        Qs[r0 + 0][lk] = q0.x; Qs[r0 + 1][lk] = q0.y; Qs[r0 + 2][lk] = q0.z; Qs[r0 + 3][lk] = q0.w;
        Qs[r0 + 8][lk] = q1.x; Qs[r0 + 9][lk] = q1.y; Qs[r0 + 10][lk] = q1.z; Qs[r0 + 11][lk] = q1.w;
        __syncthreads();
#pragma unroll
        for (int vv = 0; vv < 16; ++vv) {
            float4 a0 = *(const float4*)&Ps[vv][tm << 2];
            float4 a1 = *(const float4*)&Ps[vv][64 + (tm << 2)];
            float4 b0 = *(const float4*)&Qs[vv][tn << 2];
            float4 b1 = *(const float4*)&Qs[vv][64 + (tn << 2)];
            float a[8] = {a0.x, a0.y, a0.z, a0.w, a1.x, a1.y, a1.z, a1.w};
            float bb[8] = {b0.x, b0.y, b0.z, b0.w, b1.x, b1.y, b1.z, b1.w};
#pragma unroll
            for (int i = 0; i < 8; ++i)
#pragma unroll
                for (int j = 0; j < 8; ++j) acc[i][j] += a[i] * bb[j];
        }
    }
#pragma unroll
    for (int i = 0; i < 8; ++i) {
        const int row = (i < 4) ? ((tm << 2) + i) : (64 + (tm << 2) + i - 4);
        float4 o0 = {acc[i][0], acc[i][1], acc[i][2], acc[i][3]};
        float4 o1 = {acc[i][4], acc[i][5], acc[i][6], acc[i][7]};
        *(float4*)(out + (size_t)row * K_ + (tn << 2)) = o0;
        *(float4*)(out + (size_t)row * K_ + 64 + (tn << 2)) = o1;
    }
}

// Bordered LDL^T: row 128 of the smem matrix carries the rhs; the factor loop
// simultaneously performs the forward substitution. 1 barrier per step.
__global__ __launch_bounds__(128)
void solve(const float* __restrict__ evx, const float* __restrict__ evy,
           float* __restrict__ outp)
{
    extern __shared__ float Ml[];          // LD x LD, row-major, stride 129
    float* ws = Ml + LD * LD;              // K_ floats

    const int b = blockIdx.x >> 7, i = blockIdx.x & 127;
    const int t = threadIdx.x;

    const float s = fmaxf(evx[b * K_ + K_ - 1], evy[b * K_ + K_ - 1]);
    const float g1 = sqrtf(evx[b * K_ + t] / s);
    const float g2 = sqrtf(evy[b * K_ + i] / s);
    const float d1 = g1 * g1 + 1.0f, d2 = g2 * g2 + 1.0f;
    const float re = g2 / d2 - g1 / d1;
    const float im = 1.0f / d2 - 1.0f / d1;
    const float dg = LAMBDA * (re * re + im * im);

    const float* X0 = g_AA2 + ((size_t)(0 * B_ + b) * K_) * K_;
    const float* X1 = g_AA2 + ((size_t)(2 * B_ + b) * K_) * K_;
    for (int m = 0; m < K_; ++m)
        Ml[m * LD + t] = X0[m * K_ + t] + X1[m * K_ + t] + (t == m ? dg : 0.0f);
    const float* Y0 = g_AA2 + ((size_t)(1 * B_ + b) * K_ + i) * K_;
    const float* Y1 = g_AA2 + ((size_t)(3 * B_ + b) * K_ + i) * K_;
    Ml[K_ * LD + t] = Y0[t] + Y1[t];       // bordered rhs row

    // factorization + fused forward substitution
    for (int j = 0; j < K_; ++j) {
        __syncthreads();
        const float inv = __frcp_rn(Ml[j * LD + j]);
        if (t > j) {
            const float cj = Ml[t * LD + j] * inv;
            float* row = Ml + t * LD;
            const float* col = Ml + j;
            for (int l = j + 1; l <= t; ++l)
                row[l] -= cj * col[l * LD];
        }
        if (t == 0 && j < K_ - 1) {        // rhs row: z = L^{-1} b
            const float cj = Ml[K_ * LD + j] * inv;
            float* row = Ml + K_ * LD;
            const float* col = Ml + j;
            for (int l = j + 1; l < K_; ++l)
                row[l] -= cj * col[l * LD];
        }
    }
    __syncthreads();

    const float invd_t = __frcp_rn(Ml[t * LD + t]);
    ws[t] = Ml[K_ * LD + t] * invd_t;      // w = D^{-1} z

    // backward: L^T x = w ; L[j][t] = Ml[j*LD+t] / d_t
    for (int j = K_ - 1; j >= 1; --j) {
        __syncthreads();
        if (t < j) ws[t] -= Ml[j * LD + t] * invd_t * ws[j];
    }
    __syncthreads();
    outp[((size_t)(b * K_ + i)) * K_ + t] = ws[t];
}

extern "C" void kernel_launch(void* const* d_in, const int* in_sizes, int n_in,
                              void* d_out, int out_size)
{
    const float* fx  = (const float*)d_in[0];
    const float* fy  = (const float*)d_in[1];
    const float* evx = (const float*)d_in[2];
    const float* evy = (const float*)d_in[3];
    const float* ex  = (const float*)d_in[4];
    const float* ey  = (const float*)d_in[5];
    float* out = (float*)d_out;

    static int attr_done = 0;
    if (!attr_done) {
        cudaFuncSetAttribute(solve, cudaFuncAttributeMaxDynamicSharedMemorySize, SOLVE_SMEM);
        attr_done = 1;
    }

    gemm1<<<dim3(NCHUNK, 2, 8), 256>>>(fx, fy, ex, ey);
    reduceA<<<(8 * K_ * C_) / 256, 256>>>();
    gemm2<<<dim3(2, 8), 256>>>();
    solve<<<B_ * K_, 128, SOLVE_SMEM>>>(evx, evy, out);
}

// round 5
// speedup vs baseline: 1.0434x; 1.0434x over previous
#include <cuda_runtime.h>
#include <math.h>

#define B_ 4
#define V_ 50000
#define C_ 256
#define K_ 128
#define LAMBDA 100.0f
#define NCHUNK 19
#define TPC 165
#define NTILES 3125
#define LDI 129

__device__ float g_part1[(size_t)NCHUNK * 8 * K_ * C_];
__device__ float g_A[8 * K_ * C_];
__device__ float g_AA2[2 * 2 * B_ * K_ * K_];
__device__ float g_Ginv[B_ * K_ * K_];
__device__ float g_X0[B_ * K_ * K_];
__device__ float g_X1[B_ * K_ * K_];

__global__ __launch_bounds__(256, 2)
void gemm1(const float* __restrict__ fx, const float* __restrict__ fy,
           const float* __restrict__ ex, const float* __restrict__ ey)
{
    const int chunk = blockIdx.x, ntile = blockIdx.y, p = blockIdx.z;
    const int b = p >> 1, which = p & 1;
    const float* E = (which ? ey : ex) + (size_t)b * K_ * V_;
    const float* F = (which ? fy : fx) + (size_t)b * V_ * C_ + ntile * 128;
    float* out = g_part1 + ((size_t)chunk * 8 + which * 4 + b) * K_ * C_ + ntile * 128;

    __shared__ float Es[16][132];
    __shared__ float Fs[16][128];

    const int tid = threadIdx.x;
    const int lk = tid >> 1, lq = tid & 1;
    const int fr = tid >> 5, fc = (tid & 31) << 2;
    const int tm = tid >> 4, tn = tid & 15;
    const float* Erow = E + (size_t)lk * V_;

    float acc[8][8];
#pragma unroll
    for (int i = 0; i < 8; ++i)
#pragma unroll
        for (int j = 0; j < 8; ++j) acc[i][j] = 0.0f;

    const int t0 = chunk * TPC;
    const int t1 = (t0 + TPC < NTILES) ? (t0 + TPC) : NTILES;

    for (int t = t0; t < t1; ++t) {
        const int v = t << 4;
        float4 e0 = *(const float4*)(Erow + v + (lq << 2));
        float4 e1 = *(const float4*)(Erow + v + (lq << 2) + 8);
        float4 f0 = *(const float4*)(F + (size_t)(v + fr) * C_ + fc);
        float4 f1 = *(const float4*)(F + (size_t)(v + fr + 8) * C_ + fc);
        __syncthreads();
        const int r0 = lq << 2;
        Es[r0 + 0][lk] = e0.x; Es[r0 + 1][lk] = e0.y;
        Es[r0 + 2][lk] = e0.z; Es[r0 + 3][lk] = e0.w;
        Es[r0 + 8][lk] = e1.x; Es[r0 + 9][lk] = e1.y;
        Es[r0 + 10][lk] = e1.z; Es[r0 + 11][lk] = e1.w;
        *(float4*)&Fs[fr][fc] = f0;
        *(float4*)&Fs[fr + 8][fc] = f1;
        __syncthreads();
#pragma unroll
        for (int vv = 0; vv < 16; ++vv) {
            float4 a0 = *(const float4*)&Es[vv][tm << 2];
            float4 a1 = *(const float4*)&Es[vv][64 + (tm << 2)];
            float4 b0 = *(const float4*)&Fs[vv][tn << 2];
            float4 b1 = *(const float4*)&Fs[vv][64 + (tn << 2)];
            float a[8] = {a0.x, a0.y, a0.z, a0.w, a1.x, a1.y, a1.z, a1.w};
            float bb[8] = {b0.x, b0.y, b0.z, b0.w, b1.x, b1.y, b1.z, b1.w};
#pragma unroll
            for (int i = 0; i < 8; ++i)
#pragma unroll
                for (int j = 0; j < 8; ++j) acc[i][j] += a[i] * bb[j];
        }
    }
#pragma unroll
    for (int i = 0; i < 8; ++i) {
        const int row = (i < 4) ? ((tm << 2) + i) : (64 + (tm << 2) + i - 4);
        float4 o0 = {acc[i][0], acc[i][1], acc[i][2], acc[i][3]};
        float4 o1 = {acc[i][4], acc[i][5], acc[i][6], acc[i][7]};
        *(float4*)(out + (size_t)row * C_ + (tn << 2)) = o0;
        *(float4*)(out + (size_t)row * C_ + 64 + (tn << 2)) = o1;
    }
}

__global__ void reduceA()
{
    const int i = blockIdx.x * 256 + threadIdx.x;
    float s = 0.0f;
#pragma unroll
    for (int c = 0; c < NCHUNK; ++c) s += g_part1[(size_t)c * 8 * K_ * C_ + i];
    g_A[i] = s;
}

__global__ __launch_bounds__(256, 2)
void gemm2()
{
    const int cc = blockIdx.x;
    const int t = blockIdx.y & 1, b = blockIdx.y >> 1;
    const float* P = g_A + ((size_t)(t * B_ + b) * K_) * C_ + cc * 128;
    const float* Q = g_A + ((size_t)b * K_) * C_ + cc * 128;
    float* out = g_AA2 + ((size_t)((cc * 2 + t) * B_ + b) * K_) * K_;

    __shared__ float Ps[16][132];
    __shared__ float Qs[16][132];
    const int tid = threadIdx.x;
    const int lk = tid >> 1, lq = tid & 1;
    const int tm = tid >> 4, tn = tid & 15;

    float acc[8][8];
#pragma unroll
    for (int i = 0; i < 8; ++i)
#pragma unroll
        for (int j = 0; j < 8; ++j) acc[i][j] = 0.0f;

    for (int kt = 0; kt < 8; ++kt) {
        const int c = kt << 4;
        float4 p0 = *(const float4*)(P + (size_t)lk * C_ + c + (lq << 2));
        float4 p1 = *(const float4*)(P + (size_t)lk * C_ + c + (lq << 2) + 8);
        float4 q0 = *(const float4*)(Q + (size_t)lk * C_ + c + (lq << 2));
        float4 q1 = *(const float4*)(Q + (size_t)lk * C_ + c + (lq << 2) + 8);
        __syncthreads();
        const int r0 = lq << 2;
        Ps[r0 + 0][lk] = p0.x; Ps[r0 + 1][lk] = p0.y; Ps[r0 + 2][lk] = p0.z; Ps[r0 + 3][lk] = p0.w;
        Ps[r0 + 8][lk] = p1.x; Ps[r0 + 9][lk] = p1.y; Ps[r0 + 10][lk] = p1.z; Ps[r0 + 11][lk] = p1.w;
        Qs[r0 + 0][lk] = q0.x; Qs[r0 + 1][lk] = q0.y; Qs[r0 + 2][lk] = q0.z; Qs[r0 + 3][lk] = q0.w;
        Qs[r0 + 8][lk] = q1.x; Qs[r0 + 9][lk] = q1.y; Qs[r0 + 10][lk] = q1.z; Qs[r0 + 11][lk] = q1.w;
        __syncthreads();
#pragma unroll
        for (int vv = 0; vv < 16; ++vv) {
            float4 a0 = *(const float4*)&Ps[vv][tm << 2];
            float4 a1 = *(const float4*)&Ps[vv][64 + (tm << 2)];
            float4 b0 = *(const float4*)&Qs[vv][tn << 2];
            float4 b1 = *(const float4*)&Qs[vv][64 + (tn << 2)];
            float a[8] = {a0.x, a0.y, a0.z, a0.w, a1.x, a1.y, a1.z, a1.w};
            float bb[8] = {b0.x, b0.y, b0.z, b0.w, b1.x, b1.y, b1.z, b1.w};
#pragma unroll
            for (int i = 0; i < 8; ++i)
#pragma unroll
                for (int j = 0; j < 8; ++j) acc[i][j] += a[i] * bb[j];
        }
    }
#pragma unroll
    for (int i = 0; i < 8; ++i) {
        const int row = (i < 4) ? ((tm << 2) + i) : (64 + (tm << 2) + i - 4);
        float4 o0 = {acc[i][0], acc[i][1], acc[i][2], acc[i][3]};
        float4 o1 = {acc[i][4], acc[i][5], acc[i][6], acc[i][7]};
        *(float4*)(out + (size_t)row * K_ + (tn << 2)) = o0;
        *(float4*)(out + (size_t)row * K_ + 64 + (tn << 2)) = o1;
    }
}

// ---------------------------------------------------------------------------
// Per-batch explicit inverse of G = AA_xx (no mask): LDL^T factor, Y = L^-1,
// Ginv = Y^T D^-1 Y. One CTA per batch, 256 threads (2 per row).
// ---------------------------------------------------------------------------
__global__ __launch_bounds__(256)
void inv_kernel()
{
    extern __shared__ float sm[];
    float* M = sm;                 // K_ x LDI
    float* Y = sm + K_ * LDI;      // K_ x LDI
    __shared__ float invd[K_];

    const int b = blockIdx.x;
    const int tid = threadIdx.x;
    const int half = tid >> 7, t = tid & 127;

    const float* X0 = g_AA2 + ((size_t)(0 * B_ + b) * K_) * K_;
    const float* X1 = g_AA2 + ((size_t)(2 * B_ + b) * K_) * K_;
    for (int idx = tid; idx < K_ * K_; idx += 256) {
        const int m = idx >> 7, c = idx & 127;
        M[m * LDI + c] = X0[idx] + X1[idx];
    }
    __syncthreads();

    // LDL^T (lower triangle in place; c = M[t][j]/d_j, trailing update)
    for (int j = 0; j < K_; ++j) {
        const float inv = __frcp_rn(M[j * LDI + j]);
        if (t > j) {
            const float cf = M[t * LDI + j] * inv;
            for (int l = j + 1 + half; l <= t; l += 2)
                M[t * LDI + l] -= cf * M[l * LDI + j];
        }
        __syncthreads();
    }
    if (tid < K_) invd[tid] = __frcp_rn(M[tid * LDI + tid]);
    for (int idx = tid; idx < K_ * K_; idx += 256) {
        const int r = idx >> 7, c = idx & 127;
        Y[r * LDI + c] = (r == c) ? 1.0f : 0.0f;
    }
    __syncthreads();

    // Y = L^-1 (unit lower): forward elimination, row j final at step j
    for (int j = 0; j < K_ - 1; ++j) {
        if (t > j) {
            const float ltj = M[t * LDI + j] * invd[j];
            for (int c = half; c <= j; c += 2)
                Y[t * LDI + c] -= ltj * Y[j * LDI + c];
        }
        __syncthreads();
    }

    // Ginv[a][c] = sum_{l>=max(a,c)} Y[l][a] * Y[l][c] * invd[l]
    float* G = g_Ginv + (size_t)b * K_ * K_;
    for (int idx = tid; idx < K_ * K_; idx += 256) {
        const int a = idx >> 7, c = idx & 127;
        float s = 0.0f;
        for (int l = (a > c ? a : c); l < K_; ++l)
            s += Y[l * LDI + a] * Y[l * LDI + c] * invd[l];
        G[idx] = s;
    }
}

// ---------------------------------------------------------------------------
// Refinement GEMM: Xout = (R - D.Xin) * Ginv   (per batch; D.X elementwise)
// R[i][l] = AA_yx[b][i][l];  D scale = LAMBDA*mask(i,l). first=1 -> W = R.
// ---------------------------------------------------------------------------
__global__ __launch_bounds__(256)
void refine(const float* __restrict__ evx, const float* __restrict__ evy,
            const float* __restrict__ Xin, float* __restrict__ Xout, int first)
{
    const int b = blockIdx.x;
    __shared__ float Ws[16][132];
    __shared__ float Gs[16][128];
    __shared__ float ga[K_], gb[K_], ya[K_], yb[K_];

    const int tid = threadIdx.x;
    if (tid < K_) {
        const float s = fmaxf(evx[b * K_ + K_ - 1], evy[b * K_ + K_ - 1]);
        const float g1 = sqrtf(evx[b * K_ + tid] / s);
        const float h1 = 1.0f / (g1 * g1 + 1.0f);
        ga[tid] = g1 * h1; gb[tid] = h1;
        const float g2 = sqrtf(evy[b * K_ + tid] / s);
        const float h2 = 1.0f / (g2 * g2 + 1.0f);
        ya[tid] = g2 * h2; yb[tid] = h2;
    }
    const float* Y0 = g_AA2 + ((size_t)(1 * B_ + b) * K_) * K_;
    const float* Y1 = g_AA2 + ((size_t)(3 * B_ + b) * K_) * K_;
    const float* Gv = g_Ginv + (size_t)b * K_ * K_;
    const float* Xi = Xin + (size_t)b * K_ * K_;

    const int lk = tid >> 1, lq = tid & 1;
    const int fr = tid >> 5, fc = (tid & 31) << 2;
    const int tm = tid >> 4, tn = tid & 15;

    float acc[8][8];
#pragma unroll
    for (int i = 0; i < 8; ++i)
#pragma unroll
        for (int j = 0; j < 8; ++j) acc[i][j] = 0.0f;
    __syncthreads();   // mask tables ready

    for (int kt = 0; kt < 8; ++kt) {
        const int l0 = kt << 4;
        float w[8];
#pragma unroll
        for (int q = 0; q < 2; ++q)
#pragma unroll
            for (int e = 0; e < 4; ++e) {
                const int l = l0 + (lq << 2) + (q << 3) + e;
                float r = Y0[lk * K_ + l] + Y1[lk * K_ + l];
                if (!first) {
                    const float mre = ya[lk] - ga[l];
                    const float mim = yb[lk] - gb[l];
                    r -= LAMBDA * (mre * mre + mim * mim) * Xi[lk * K_ + l];
                }
                w[(q << 2) + e] = r;
            }
        float4 q0 = *(const float4*)(Gv + (size_t)(l0 + fr) * K_ + fc);
        float4 q1 = *(const float4*)(Gv + (size_t)(l0 + fr + 8) * K_ + fc);
        __syncthreads();
        const int r0 = lq << 2;
        Ws[r0 + 0][lk] = w[0]; Ws[r0 + 1][lk] = w[1];
        Ws[r0 + 2][lk] = w[2]; Ws[r0 + 3][lk] = w[3];
        Ws[r0 + 8][lk] = w[4]; Ws[r0 + 9][lk] = w[5];
        Ws[r0 + 10][lk] = w[6]; Ws[r0 + 11][lk] = w[7];
        *(float4*)&Gs[fr][fc] = q0;
        *(float4*)&Gs[fr + 8][fc] = q1;
        __syncthreads();
#pragma unroll
        for (int vv = 0; vv < 16; ++vv) {
            float4 a0 = *(const float4*)&Ws[vv][tm << 2];
            float4 a1 = *(const float4*)&Ws[vv][64 + (tm << 2)];
            float4 b0 = *(const float4*)&Gs[vv][tn << 2];
            float4 b1 = *(const float4*)&Gs[vv][64 + (tn << 2)];
            float a[8] = {a0.x, a0.y, a0.z, a0.w, a1.x, a1.y, a1.z, a1.w};
            float bb[8] = {b0.x, b0.y, b0.z, b0.w, b1.x, b1.y, b1.z, b1.w};
#pragma unroll
            for (int i = 0; i < 8; ++i)
#pragma unroll
                for (int j = 0; j < 8; ++j) acc[i][j] += a[i] * bb[j];
        }
    }
    float* Xo = Xout + (size_t)b * K_ * K_;
#pragma unroll
    for (int i = 0; i < 8; ++i) {
        const int row = (i < 4) ? ((tm << 2) + i) : (64 + (tm << 2) + i - 4);
        float4 o0 = {acc[i][0], acc[i][1], acc[i][2], acc[i][3]};
        float4 o1 = {acc[i][4], acc[i][5], acc[i][6], acc[i][7]};
        *(float4*)(Xo + (size_t)row * K_ + (tn << 2)) = o0;
        *(float4*)(Xo + (size_t)row * K_ + 64 + (tn << 2)) = o1;
    }
}

extern "C" void kernel_launch(void* const* d_in, const int* in_sizes, int n_in,
                              void* d_out, int out_size)
{
    const float* fx  = (const float*)d_in[0];
    const float* fy  = (const float*)d_in[1];
    const float* evx = (const float*)d_in[2];
    const float* evy = (const float*)d_in[3];
    const float* ex  = (const float*)d_in[4];
    const float* ey  = (const float*)d_in[5];
    float* out = (float*)d_out;

    static int attr_done = 0;
    if (!attr_done) {
        cudaFuncSetAttribute(inv_kernel, cudaFuncAttributeMaxDynamicSharedMemorySize,
                             2 * K_ * LDI * (int)sizeof(float));
        attr_done = 1;
    }

    gemm1<<<dim3(NCHUNK, 2, 8), 256>>>(fx, fy, ex, ey);
    reduceA<<<(8 * K_ * C_) / 256, 256>>>();
    gemm2<<<dim3(2, 8), 256>>>();
    inv_kernel<<<B_, 256, 2 * K_ * LDI * sizeof(float)>>>();
    refine<<<B_, 256>>>(evx, evy, g_X0, g_X0, 1);
    refine<<<B_, 256>>>(evx, evy, g_X0, g_X1, 0);
    refine<<<B_, 256>>>(evx, evy, g_X1, out, 0);
}

// round 6
// speedup vs baseline: 1.4203x; 1.3613x over previous
#include <cuda_runtime.h>
#include <math.h>

#define B_ 4
#define V_ 50000
#define C_ 256
#define K_ 128
#define LAMBDA 100.0f
#define NCHUNK 19
#define TPC 165
#define NTILES 3125
#define LDI 129

__device__ float g_part1[(size_t)NCHUNK * 8 * K_ * C_];
__device__ float g_A[8 * K_ * C_];
__device__ float g_AA2[2 * 2 * B_ * K_ * K_];
__device__ float g_Lc[B_ * K_ * K_];    // L col-major: g_Lc[b][j*128+t]
__device__ float g_invd[B_ * K_];

__global__ __launch_bounds__(256, 2)
void gemm1(const float* __restrict__ fx, const float* __restrict__ fy,
           const float* __restrict__ ex, const float* __restrict__ ey)
{
    const int chunk = blockIdx.x, ntile = blockIdx.y, p = blockIdx.z;
    const int b = p >> 1, which = p & 1;
    const float* E = (which ? ey : ex) + (size_t)b * K_ * V_;
    const float* F = (which ? fy : fx) + (size_t)b * V_ * C_ + ntile * 128;
    float* out = g_part1 + ((size_t)chunk * 8 + which * 4 + b) * K_ * C_ + ntile * 128;

    __shared__ float Es[16][132];
    __shared__ float Fs[16][128];

    const int tid = threadIdx.x;
    const int lk = tid >> 1, lq = tid & 1;
    const int fr = tid >> 5, fc = (tid & 31) << 2;
    const int tm = tid >> 4, tn = tid & 15;
    const float* Erow = E + (size_t)lk * V_;

    float acc[8][8];
#pragma unroll
    for (int i = 0; i < 8; ++i)
#pragma unroll
        for (int j = 0; j < 8; ++j) acc[i][j] = 0.0f;

    const int t0 = chunk * TPC;
    const int t1 = (t0 + TPC < NTILES) ? (t0 + TPC) : NTILES;

    for (int t = t0; t < t1; ++t) {
        const int v = t << 4;
        float4 e0 = *(const float4*)(Erow + v + (lq << 2));
        float4 e1 = *(const float4*)(Erow + v + (lq << 2) + 8);
        float4 f0 = *(const float4*)(F + (size_t)(v + fr) * C_ + fc);
        float4 f1 = *(const float4*)(F + (size_t)(v + fr + 8) * C_ + fc);
        __syncthreads();
        const int r0 = lq << 2;
        Es[r0 + 0][lk] = e0.x; Es[r0 + 1][lk] = e0.y;
        Es[r0 + 2][lk] = e0.z; Es[r0 + 3][lk] = e0.w;
        Es[r0 + 8][lk] = e1.x; Es[r0 + 9][lk] = e1.y;
        Es[r0 + 10][lk] = e1.z; Es[r0 + 11][lk] = e1.w;
        *(float4*)&Fs[fr][fc] = f0;
        *(float4*)&Fs[fr + 8][fc] = f1;
        __syncthreads();
#pragma unroll
        for (int vv = 0; vv < 16; ++vv) {
            float4 a0 = *(const float4*)&Es[vv][tm << 2];
            float4 a1 = *(const float4*)&Es[vv][64 + (tm << 2)];
            float4 b0 = *(const float4*)&Fs[vv][tn << 2];
            float4 b1 = *(const float4*)&Fs[vv][64 + (tn << 2)];
            float a[8] = {a0.x, a0.y, a0.z, a0.w, a1.x, a1.y, a1.z, a1.w};
            float bb[8] = {b0.x, b0.y, b0.z, b0.w, b1.x, b1.y, b1.z, b1.w};
#pragma unroll
            for (int i = 0; i < 8; ++i)
#pragma unroll
                for (int j = 0; j < 8; ++j) acc[i][j] += a[i] * bb[j];
        }
    }
#pragma unroll
    for (int i = 0; i < 8; ++i) {
        const int row = (i < 4) ? ((tm << 2) + i) : (64 + (tm << 2) + i - 4);
        float4 o0 = {acc[i][0], acc[i][1], acc[i][2], acc[i][3]};
        float4 o1 = {acc[i][4], acc[i][5], acc[i][6], acc[i][7]};
        *(float4*)(out + (size_t)row * C_ + (tn << 2)) = o0;
        *(float4*)(out + (size_t)row * C_ + 64 + (tn << 2)) = o1;
    }
}

__global__ void reduceA()
{
    const int i = blockIdx.x * 256 + threadIdx.x;
    float s = 0.0f;
#pragma unroll
    for (int c = 0; c < NCHUNK; ++c) s += g_part1[(size_t)c * 8 * K_ * C_ + i];
    g_A[i] = s;
}

__global__ __launch_bounds__(256, 2)
void gemm2()
{
    const int cc = blockIdx.x;
    const int t = blockIdx.y & 1, b = blockIdx.y >> 1;
    const float* P = g_A + ((size_t)(t * B_ + b) * K_) * C_ + cc * 128;
    const float* Q = g_A + ((size_t)b * K_) * C_ + cc * 128;
    float* out = g_AA2 + ((size_t)((cc * 2 + t) * B_ + b) * K_) * K_;

    __shared__ float Ps[16][132];
    __shared__ float Qs[16][132];
    const int tid = threadIdx.x;
    const int lk = tid >> 1, lq = tid & 1;
    const int tm = tid >> 4, tn = tid & 15;

    float acc[8][8];
#pragma unroll
    for (int i = 0; i < 8; ++i)
#pragma unroll
        for (int j = 0; j < 8; ++j) acc[i][j] = 0.0f;

    for (int kt = 0; kt < 8; ++kt) {
        const int c = kt << 4;
        float4 p0 = *(const float4*)(P + (size_t)lk * C_ + c + (lq << 2));
        float4 p1 = *(const float4*)(P + (size_t)lk * C_ + c + (lq << 2) + 8);
        float4 q0 = *(const float4*)(Q + (size_t)lk * C_ + c + (lq << 2));
        float4 q1 = *(const float4*)(Q + (size_t)lk * C_ + c + (lq << 2) + 8);
        __syncthreads();
        const int r0 = lq << 2;
        Ps[r0 + 0][lk] = p0.x; Ps[r0 + 1][lk] = p0.y; Ps[r0 + 2][lk] = p0.z; Ps[r0 + 3][lk] = p0.w;
        Ps[r0 + 8][lk] = p1.x; Ps[r0 + 9][lk] = p1.y; Ps[r0 + 10][lk] = p1.z; Ps[r0 + 11][lk] = p1.w;
        Qs[r0 + 0][lk] = q0.x; Qs[r0 + 1][lk] = q0.y; Qs[r0 + 2][lk] = q0.z; Qs[r0 + 3][lk] = q0.w;
        Qs[r0 + 8][lk] = q1.x; Qs[r0 + 9][lk] = q1.y; Qs[r0 + 10][lk] = q1.z; Qs[r0 + 11][lk] = q1.w;
        __syncthreads();
#pragma unroll
        for (int vv = 0; vv < 16; ++vv) {
            float4 a0 = *(const float4*)&Ps[vv][tm << 2];
            float4 a1 = *(const float4*)&Ps[vv][64 + (tm << 2)];
            float4 b0 = *(const float4*)&Qs[vv][tn << 2];
            float4 b1 = *(const float4*)&Qs[vv][64 + (tn << 2)];
            float a[8] = {a0.x, a0.y, a0.z, a0.w, a1.x, a1.y, a1.z, a1.w};
            float bb[8] = {b0.x, b0.y, b0.z, b0.w, b1.x, b1.y, b1.z, b1.w};
#pragma unroll
            for (int i = 0; i < 8; ++i)
#pragma unroll
                for (int j = 0; j < 8; ++j) acc[i][j] += a[i] * bb[j];
        }
    }
#pragma unroll
    for (int i = 0; i < 8; ++i) {
        const int row = (i < 4) ? ((tm << 2) + i) : (64 + (tm << 2) + i - 4);
        float4 o0 = {acc[i][0], acc[i][1], acc[i][2], acc[i][3]};
        float4 o1 = {acc[i][4], acc[i][5], acc[i][6], acc[i][7]};
        *(float4*)(out + (size_t)row * K_ + (tn << 2)) = o0;
        *(float4*)(out + (size_t)row * K_ + 64 + (tn << 2)) = o1;
    }
}

// LDL^T of G = AA_xx per batch. 256 threads = 2 per row. 1 barrier/step.
__global__ __launch_bounds__(256)
void factor()
{
    __shared__ float M[K_ * LDI];
    __shared__ float sinvd[K_];
    const int b = blockIdx.x, tid = threadIdx.x;
    const int half = tid >> 7, t = tid & 127;

    const float* X0 = g_AA2 + ((size_t)(0 * B_ + b) * K_) * K_;
    const float* X1 = g_AA2 + ((size_t)(2 * B_ + b) * K_) * K_;
    for (int idx = tid; idx < K_ * K_; idx += 256) {
        const int m = idx >> 7, c = idx & 127;
        M[m * LDI + c] = X0[idx] + X1[idx];
    }
    __syncthreads();
    for (int j = 0; j < K_; ++j) {
        const float inv = __frcp_rn(M[j * LDI + j]);
        if (t > j) {
            const float cf = M[t * LDI + j] * inv;
            for (int l = j + 1 + half; l <= t; l += 2)
                M[t * LDI + l] -= cf * M[l * LDI + j];
        }
        __syncthreads();
    }
    if (tid < K_) {
        sinvd[tid] = __frcp_rn(M[tid * LDI + tid]);
        g_invd[b * K_ + tid] = sinvd[tid];
    }
    __syncthreads();
    // store L col-major normalized: Lc[j*128+t] = M[t][j]/d_j (t>j), unit diag
    float* Lc = g_Lc + (size_t)b * K_ * K_;
    for (int idx = tid; idx < K_ * K_; idx += 256) {
        const int j = idx >> 7, r = idx & 127;
        Lc[idx] = (r > j) ? M[r * LDI + j] * sinvd[j] : (r == j ? 1.0f : 0.0f);
    }
}

// One warp per output column i: 3x LDL^T substitution with in-warp Neumann
// refinement w = r - d*x. L staged in padded smem (stride 129).
__global__ __launch_bounds__(128)
void bigsolve(const float* __restrict__ evx, const float* __restrict__ evy,
              float* __restrict__ outp)
{
    extern __shared__ float Ls[];          // [j*129 + t]
    __shared__ float sinvd[K_];

    const int b = blockIdx.x >> 5, grp = blockIdx.x & 31;
    const int tid = threadIdx.x, w = tid >> 5, k = tid & 31;
    const int i = grp * 4 + w;

    const float* Lc = g_Lc + (size_t)b * K_ * K_;
    for (int idx = tid; idx < K_ * K_; idx += 128) {
        const int j = idx >> 7, t = idx & 127;
        Ls[j * LDI + t] = Lc[idx];
    }
    if (tid < K_) sinvd[tid] = g_invd[b * K_ + tid];

    // per-lane: rows t = k + 32m
    float r[4], d[4], x[4], invd_r[4];
    const float s = fmaxf(evx[b * K_ + K_ - 1], evy[b * K_ + K_ - 1]);
    const float g2 = sqrtf(evy[b * K_ + i] / s);
    const float h2 = 1.0f / (g2 * g2 + 1.0f);
    const float ya = g2 * h2, yb = h2;
    const float* Y0 = g_AA2 + ((size_t)(1 * B_ + b) * K_ + i) * K_;
    const float* Y1 = g_AA2 + ((size_t)(3 * B_ + b) * K_ + i) * K_;
#pragma unroll
    for (int m = 0; m < 4; ++m) {
        const int t = k + 32 * m;
        r[m] = Y0[t] + Y1[t];
        const float g1 = sqrtf(evx[b * K_ + t] / s);
        const float h1 = 1.0f / (g1 * g1 + 1.0f);
        const float re = ya - g1 * h1, im = yb - h1;
        d[m] = LAMBDA * (re * re + im * im);
        x[m] = 0.0f;
    }
    __syncthreads();
#pragma unroll
    for (int m = 0; m < 4; ++m) invd_r[m] = sinvd[k + 32 * m];

    for (int it = 0; it < 3; ++it) {
        float y[4];
#pragma unroll
        for (int m = 0; m < 4; ++m) y[m] = r[m] - d[m] * x[m];
        // forward: L y = w
#pragma unroll
        for (int q = 0; q < 4; ++q)
            for (int j2 = 0; j2 < 32; ++j2) {
                const int j = q * 32 + j2;
                const float yj = __shfl_sync(0xFFFFFFFFu, y[q], j2);
#pragma unroll
                for (int m = 0; m < 4; ++m)
                    if (m > q || (m == q && k > j2))
                        y[m] -= Ls[j * LDI + k + 32 * m] * yj;
            }
        // diag
#pragma unroll
        for (int m = 0; m < 4; ++m) y[m] *= invd_r[m];
        // backward: L^T x = y  (L[j][t] = Ls[t*129 + j])
#pragma unroll
        for (int q = 3; q >= 0; --q)
            for (int j2 = 31; j2 >= 0; --j2) {
                const int j = q * 32 + j2;
                const float yj = __shfl_sync(0xFFFFFFFFu, y[q], j2);
#pragma unroll
                for (int m = 0; m < 4; ++m)
                    if (m < q || (m == q && k < j2))
                        y[m] -= Ls[(k + 32 * m) * LDI + j] * yj;
            }
#pragma unroll
        for (int m = 0; m < 4; ++m) x[m] = y[m];
    }
    float* o = outp + ((size_t)(b * K_ + i)) * K_;
#pragma unroll
    for (int m = 0; m < 4; ++m) o[k + 32 * m] = x[m];
}

extern "C" void kernel_launch(void* const* d_in, const int* in_sizes, int n_in,
                              void* d_out, int out_size)
{
    const float* fx  = (const float*)d_in[0];
    const float* fy  = (const float*)d_in[1];
    const float* evx = (const float*)d_in[2];
    const float* evy = (const float*)d_in[3];
    const float* ex  = (const float*)d_in[4];
    const float* ey  = (const float*)d_in[5];
    float* out = (float*)d_out;

    static int attr_done = 0;
    if (!attr_done) {
        cudaFuncSetAttribute(bigsolve, cudaFuncAttributeMaxDynamicSharedMemorySize,
                             K_ * LDI * (int)sizeof(float));
        attr_done = 1;
    }

    gemm1<<<dim3(NCHUNK, 2, 8), 256>>>(fx, fy, ex, ey);
    reduceA<<<(8 * K_ * C_) / 256, 256>>>();
    gemm2<<<dim3(2, 8), 256>>>();
    factor<<<B_, 256>>>();
    bigsolve<<<B_ * 32, 128, K_ * LDI * sizeof(float)>>>(evx, evy, out);
}

// round 7
// speedup vs baseline: 1.5061x; 1.0604x over previous
#include <cuda_runtime.h>
#include <math.h>

#define B_ 4
#define V_ 50000
#define C_ 256
#define K_ 128
#define LAMBDA 100.0f
#define NCHUNK 19
#define TPC 165
#define NTILES 3125
#define LDI 129

__device__ float g_part1[(size_t)NCHUNK * 8 * K_ * C_];
__device__ float g_A[8 * K_ * C_];
__device__ float g_AA2[2 * 2 * B_ * K_ * K_];
__device__ float g_Lc[B_ * K_ * K_];    // L col-major, unit diag: g_Lc[b][j*128+t]
__device__ float g_invd[B_ * K_];

__global__ __launch_bounds__(256, 2)
void gemm1(const float* __restrict__ fx, const float* __restrict__ fy,
           const float* __restrict__ ex, const float* __restrict__ ey)
{
    const int chunk = blockIdx.x, ntile = blockIdx.y, p = blockIdx.z;
    const int b = p >> 1, which = p & 1;
    const float* E = (which ? ey : ex) + (size_t)b * K_ * V_;
    const float* F = (which ? fy : fx) + (size_t)b * V_ * C_ + ntile * 128;
    float* out = g_part1 + ((size_t)chunk * 8 + which * 4 + b) * K_ * C_ + ntile * 128;

    __shared__ float Es[16][132];
    __shared__ float Fs[16][128];

    const int tid = threadIdx.x;
    const int lk = tid >> 1, lq = tid & 1;
    const int fr = tid >> 5, fc = (tid & 31) << 2;
    const int tm = tid >> 4, tn = tid & 15;
    const float* Erow = E + (size_t)lk * V_;

    float acc[8][8];
#pragma unroll
    for (int i = 0; i < 8; ++i)
#pragma unroll
        for (int j = 0; j < 8; ++j) acc[i][j] = 0.0f;

    const int t0 = chunk * TPC;
    const int t1 = (t0 + TPC < NTILES) ? (t0 + TPC) : NTILES;

    for (int t = t0; t < t1; ++t) {
        const int v = t << 4;
        float4 e0 = *(const float4*)(Erow + v + (lq << 2));
        float4 e1 = *(const float4*)(Erow + v + (lq << 2) + 8);
        float4 f0 = *(const float4*)(F + (size_t)(v + fr) * C_ + fc);
        float4 f1 = *(const float4*)(F + (size_t)(v + fr + 8) * C_ + fc);
        __syncthreads();
        const int r0 = lq << 2;
        Es[r0 + 0][lk] = e0.x; Es[r0 + 1][lk] = e0.y;
        Es[r0 + 2][lk] = e0.z; Es[r0 + 3][lk] = e0.w;
        Es[r0 + 8][lk] = e1.x; Es[r0 + 9][lk] = e1.y;
        Es[r0 + 10][lk] = e1.z; Es[r0 + 11][lk] = e1.w;
        *(float4*)&Fs[fr][fc] = f0;
        *(float4*)&Fs[fr + 8][fc] = f1;
        __syncthreads();
#pragma unroll
        for (int vv = 0; vv < 16; ++vv) {
            float4 a0 = *(const float4*)&Es[vv][tm << 2];
            float4 a1 = *(const float4*)&Es[vv][64 + (tm << 2)];
            float4 b0 = *(const float4*)&Fs[vv][tn << 2];
            float4 b1 = *(const float4*)&Fs[vv][64 + (tn << 2)];
            float a[8] = {a0.x, a0.y, a0.z, a0.w, a1.x, a1.y, a1.z, a1.w};
            float bb[8] = {b0.x, b0.y, b0.z, b0.w, b1.x, b1.y, b1.z, b1.w};
#pragma unroll
            for (int i = 0; i < 8; ++i)
#pragma unroll
                for (int j = 0; j < 8; ++j) acc[i][j] += a[i] * bb[j];
        }
    }
#pragma unroll
    for (int i = 0; i < 8; ++i) {
        const int row = (i < 4) ? ((tm << 2) + i) : (64 + (tm << 2) + i - 4);
        float4 o0 = {acc[i][0], acc[i][1], acc[i][2], acc[i][3]};
        float4 o1 = {acc[i][4], acc[i][5], acc[i][6], acc[i][7]};
        *(float4*)(out + (size_t)row * C_ + (tn << 2)) = o0;
        *(float4*)(out + (size_t)row * C_ + 64 + (tn << 2)) = o1;
    }
}

__global__ void reduceA()
{
    const int i = blockIdx.x * 256 + threadIdx.x;
    float s = 0.0f;
#pragma unroll
    for (int c = 0; c < NCHUNK; ++c) s += g_part1[(size_t)c * 8 * K_ * C_ + i];
    g_A[i] = s;
}

__global__ __launch_bounds__(256, 2)
void gemm2()
{
    const int cc = blockIdx.x;
    const int t = blockIdx.y & 1, b = blockIdx.y >> 1;
    const float* P = g_A + ((size_t)(t * B_ + b) * K_) * C_ + cc * 128;
    const float* Q = g_A + ((size_t)b * K_) * C_ + cc * 128;
    float* out = g_AA2 + ((size_t)((cc * 2 + t) * B_ + b) * K_) * K_;

    __shared__ float Ps[16][132];
    __shared__ float Qs[16][132];
    const int tid = threadIdx.x;
    const int lk = tid >> 1, lq = tid & 1;
    const int tm = tid >> 4, tn = tid & 15;

    float acc[8][8];
#pragma unroll
    for (int i = 0; i < 8; ++i)
#pragma unroll
        for (int j = 0; j < 8; ++j) acc[i][j] = 0.0f;

    for (int kt = 0; kt < 8; ++kt) {
        const int c = kt << 4;
        float4 p0 = *(const float4*)(P + (size_t)lk * C_ + c + (lq << 2));
        float4 p1 = *(const float4*)(P + (size_t)lk * C_ + c + (lq << 2) + 8);
        float4 q0 = *(const float4*)(Q + (size_t)lk * C_ + c + (lq << 2));
        float4 q1 = *(const float4*)(Q + (size_t)lk * C_ + c + (lq << 2) + 8);
        __syncthreads();
        const int r0 = lq << 2;
        Ps[r0 + 0][lk] = p0.x; Ps[r0 + 1][lk] = p0.y; Ps[r0 + 2][lk] = p0.z; Ps[r0 + 3][lk] = p0.w;
        Ps[r0 + 8][lk] = p1.x; Ps[r0 + 9][lk] = p1.y; Ps[r0 + 10][lk] = p1.z; Ps[r0 + 11][lk] = p1.w;
        Qs[r0 + 0][lk] = q0.x; Qs[r0 + 1][lk] = q0.y; Qs[r0 + 2][lk] = q0.z; Qs[r0 + 3][lk] = q0.w;
        Qs[r0 + 8][lk] = q1.x; Qs[r0 + 9][lk] = q1.y; Qs[r0 + 10][lk] = q1.z; Qs[r0 + 11][lk] = q1.w;
        __syncthreads();
#pragma unroll
        for (int vv = 0; vv < 16; ++vv) {
            float4 a0 = *(const float4*)&Ps[vv][tm << 2];
            float4 a1 = *(const float4*)&Ps[vv][64 + (tm << 2)];
            float4 b0 = *(const float4*)&Qs[vv][tn << 2];
            float4 b1 = *(const float4*)&Qs[vv][64 + (tn << 2)];
            float a[8] = {a0.x, a0.y, a0.z, a0.w, a1.x, a1.y, a1.z, a1.w};
            float bb[8] = {b0.x, b0.y, b0.z, b0.w, b1.x, b1.y, b1.z, b1.w};
#pragma unroll
            for (int i = 0; i < 8; ++i)
#pragma unroll
                for (int j = 0; j < 8; ++j) acc[i][j] += a[i] * bb[j];
        }
    }
#pragma unroll
    for (int i = 0; i < 8; ++i) {
        const int row = (i < 4) ? ((tm << 2) + i) : (64 + (tm << 2) + i - 4);
        float4 o0 = {acc[i][0], acc[i][1], acc[i][2], acc[i][3]};
        float4 o1 = {acc[i][4], acc[i][5], acc[i][6], acc[i][7]};
        *(float4*)(out + (size_t)row * K_ + (tn << 2)) = o0;
        *(float4*)(out + (size_t)row * K_ + 64 + (tn << 2)) = o1;
    }
}

// ---------------------------------------------------------------------------
// Blocked LDL^T of G = AA_xx per batch. 4 rank-32 block steps:
//  (1) 32x32 diag block by warp 0 (syncwarp only)
//  (2) panel solve: one thread per row, register recurrence, NO barriers
//  (3) trailing update: parallel 32-dot-products over 256 threads
// ---------------------------------------------------------------------------
__global__ __launch_bounds__(256, 1)
void factor()
{
    __shared__ float M[K_ * LDI];       // row-major, stride 129
    __shared__ float Wd[96 * 33];       // W = L21*D panel, padded stride 33
    __shared__ float sinvd[K_];
    const int b = blockIdx.x, tid = threadIdx.x;

    const float* X0 = g_AA2 + ((size_t)(0 * B_ + b) * K_) * K_;
    const float* X1 = g_AA2 + ((size_t)(2 * B_ + b) * K_) * K_;
    for (int idx = tid; idx < K_ * K_; idx += 256) {
        const int m = idx >> 7, c = idx & 127;
        M[m * LDI + c] = X0[idx] + X1[idx];
    }
    __syncthreads();

#pragma unroll
    for (int kb = 0; kb < 4; ++kb) {
        const int j0 = kb << 5;
        // (1) diag block LDL^T in place (column entries stay unnormalized = L*d)
        if (tid < 32) {
            for (int j = 0; j < 32; ++j) {
                const float inv = __frcp_rn(M[(j0 + j) * LDI + j0 + j]);
                if (tid > j) {
                    const float cf = M[(j0 + tid) * LDI + j0 + j] * inv;
                    for (int l = j + 1; l <= tid; ++l)
                        M[(j0 + tid) * LDI + j0 + l] -= cf * M[(j0 + l) * LDI + j0 + j];
                }
                __syncwarp();
            }
            sinvd[j0 + tid] = __frcp_rn(M[(j0 + tid) * LDI + j0 + tid]);
        }
        __syncthreads();

        const int nrows = 96 - (kb << 5);
        if (nrows > 0) {
            // (2) panel solve: row i = j0+32+tid, purely thread-local recurrence
            if (tid < nrows) {
                const int i = j0 + 32 + tid;
                float w[32];
#pragma unroll
                for (int l = 0; l < 32; ++l) w[l] = M[i * LDI + j0 + l];
#pragma unroll
                for (int l = 0; l < 32; ++l) {
                    const float c = w[l] * sinvd[j0 + l];
#pragma unroll
                    for (int j = l + 1; j < 32; ++j)
                        w[j] -= c * M[(j0 + j) * LDI + j0 + l];
                }
#pragma unroll
                for (int l = 0; l < 32; ++l) {
                    M[i * LDI + j0 + l] = w[l] * sinvd[j0 + l];  // L21 normalized
                    Wd[tid * 33 + l] = w[l];                     // W = L21*D
                }
            }
            __syncthreads();

            // (3) trailing update: A22[i][c] -= sum_l L21[i][l] * W[c][l]
            const int total = nrows * nrows;
            for (int e = tid; e < total; e += 256) {
                const int ri = e / nrows, ci = e % nrows;
                if (ci <= ri) {
                    const int i = j0 + 32 + ri, c = j0 + 32 + ci;
                    float s = 0.0f;
#pragma unroll
                    for (int l = 0; l < 32; ++l)
                        s += M[i * LDI + j0 + l] * Wd[ci * 33 + l];
                    M[i * LDI + c] -= s;
                }
            }
            __syncthreads();
        }
    }

    // write outputs: Lc[j*128+r] unit-lower (normalize within-block cols), invd
    float* Lc = g_Lc + (size_t)b * K_ * K_;
    for (int idx = tid; idx < K_ * K_; idx += 256) {
        const int j = idx >> 7, r = idx & 127;
        float v;
        if (r < j)       v = 0.0f;
        else if (r == j) v = 1.0f;
        else if ((r >> 5) == (j >> 5)) v = M[r * LDI + j] * sinvd[j];
        else             v = M[r * LDI + j];
        Lc[idx] = v;
    }
    if (tid < K_) g_invd[b * K_ + tid] = sinvd[tid];
}

// One warp per output column i: 3x LDL^T substitution with in-warp Neumann
// refinement w = r - d*x. L staged in padded smem (stride 129).
__global__ __launch_bounds__(128)
void bigsolve(const float* __restrict__ evx, const float* __restrict__ evy,
              float* __restrict__ outp)
{
    extern __shared__ float Ls[];          // [j*129 + t]
    __shared__ float sinvd[K_];

    const int b = blockIdx.x >> 5, grp = blockIdx.x & 31;
    const int tid = threadIdx.x, w = tid >> 5, k = tid & 31;
    const int i = grp * 4 + w;

    const float* Lc = g_Lc + (size_t)b * K_ * K_;
    for (int idx = tid; idx < K_ * K_; idx += 128) {
        const int j = idx >> 7, t = idx & 127;
        Ls[j * LDI + t] = Lc[idx];
    }
    if (tid < K_) sinvd[tid] = g_invd[b * K_ + tid];

    float r[4], d[4], x[4], invd_r[4];
    const float s = fmaxf(evx[b * K_ + K_ - 1], evy[b * K_ + K_ - 1]);
    const float g2 = sqrtf(evy[b * K_ + i] / s);
    const float h2 = 1.0f / (g2 * g2 + 1.0f);
    const float ya = g2 * h2, yb = h2;
    const float* Y0 = g_AA2 + ((size_t)(1 * B_ + b) * K_ + i) * K_;
    const float* Y1 = g_AA2 + ((size_t)(3 * B_ + b) * K_ + i) * K_;
#pragma unroll
    for (int m = 0; m < 4; ++m) {
        const int t = k + 32 * m;
        r[m] = Y0[t] + Y1[t];
        const float g1 = sqrtf(evx[b * K_ + t] / s);
        const float h1 = 1.0f / (g1 * g1 + 1.0f);
        const float re = ya - g1 * h1, im = yb - h1;
        d[m] = LAMBDA * (re * re + im * im);
        x[m] = 0.0f;
    }
    __syncthreads();
#pragma unroll
    for (int m = 0; m < 4; ++m) invd_r[m] = sinvd[k + 32 * m];

    for (int it = 0; it < 3; ++it) {
        float y[4];
#pragma unroll
        for (int m = 0; m < 4; ++m) y[m] = r[m] - d[m] * x[m];
#pragma unroll
        for (int q = 0; q < 4; ++q)
            for (int j2 = 0; j2 < 32; ++j2) {
                const int j = q * 32 + j2;
                const float yj = __shfl_sync(0xFFFFFFFFu, y[q], j2);
#pragma unroll
                for (int m = 0; m < 4; ++m)
                    if (m > q || (m == q && k > j2))
                        y[m] -= Ls[j * LDI + k + 32 * m] * yj;
            }
#pragma unroll
        for (int m = 0; m < 4; ++m) y[m] *= invd_r[m];
#pragma unroll
        for (int q = 3; q >= 0; --q)
            for (int j2 = 31; j2 >= 0; --j2) {
                const int j = q * 32 + j2;
                const float yj = __shfl_sync(0xFFFFFFFFu, y[q], j2);
#pragma unroll
                for (int m = 0; m < 4; ++m)
                    if (m < q || (m == q && k < j2))
                        y[m] -= Ls[(k + 32 * m) * LDI + j] * yj;
            }
#pragma unroll
        for (int m = 0; m < 4; ++m) x[m] = y[m];
    }
    float* o = outp + ((size_t)(b * K_ + i)) * K_;
#pragma unroll
    for (int m = 0; m < 4; ++m) o[k + 32 * m] = x[m];
}

extern "C" void kernel_launch(void* const* d_in, const int* in_sizes, int n_in,
                              void* d_out, int out_size)
{
    const float* fx  = (const float*)d_in[0];
    const float* fy  = (const float*)d_in[1];
    const float* evx = (const float*)d_in[2];
    const float* evy = (const float*)d_in[3];
    const float* ex  = (const float*)d_in[4];
    const float* ey  = (const float*)d_in[5];
    float* out = (float*)d_out;

    static int attr_done = 0;
    if (!attr_done) {
        cudaFuncSetAttribute(bigsolve, cudaFuncAttributeMaxDynamicSharedMemorySize,
                             K_ * LDI * (int)sizeof(float));
        attr_done = 1;
    }

    gemm1<<<dim3(NCHUNK, 2, 8), 256>>>(fx, fy, ex, ey);
    reduceA<<<(8 * K_ * C_) / 256, 256>>>();
    gemm2<<<dim3(2, 8), 256>>>();
    factor<<<B_, 256>>>();
    bigsolve<<<B_ * 32, 128, K_ * LDI * sizeof(float)>>>(evx, evy, out);
}

// round 10
// speedup vs baseline: 2.3811x; 1.5810x over previous
#include <cuda_runtime.h>
#include <cuda_bf16.h>
#include <math.h>

#define B_ 4
#define V_ 50000
#define C_ 256
#define K_ 128
#define LAMBDA 100.0f
#define NCHUNK 19
#define TPC 165
#define NTILES 3125
#define LDI 129

__device__ float g_part1[(size_t)NCHUNK * 8 * K_ * C_];
__device__ float g_A[8 * K_ * C_];
__device__ float g_AA2[2 * 2 * B_ * K_ * K_];
__device__ float g_Lc[B_ * K_ * K_];
__device__ float g_invd[B_ * K_];

__device__ __forceinline__ unsigned smem_u32(const void* p) {
    unsigned a;
    asm("{ .reg .u64 t; cvta.to.shared.u64 t, %1; cvt.u32.u64 %0, t; }" : "=r"(a) : "l"(p));
    return a;
}
__device__ __forceinline__ void cvt2(float x, float y, unsigned& hi, unsigned& lo) {
    __nv_bfloat162 h = __floats2bfloat162_rn(x, y);
    __nv_bfloat162 l = __floats2bfloat162_rn(x - __bfloat162float(h.x),
                                             y - __bfloat162float(h.y));
    hi = *(unsigned*)&h;
    lo = *(unsigned*)&l;
}
__device__ __forceinline__ void ldx4(unsigned* r, unsigned a) {
    asm volatile("ldmatrix.sync.aligned.m8n8.x4.shared.b16 {%0,%1,%2,%3}, [%4];"
                 : "=r"(r[0]), "=r"(r[1]), "=r"(r[2]), "=r"(r[3]) : "r"(a));
}
__device__ __forceinline__ void ldx2t(unsigned* r, unsigned a) {
    asm volatile("ldmatrix.sync.aligned.m8n8.x2.trans.shared.b16 {%0,%1}, [%2];"
                 : "=r"(r[0]), "=r"(r[1]) : "r"(a));
}
__device__ __forceinline__ void mma16816(float* d, const unsigned* a, const unsigned* b) {
    asm volatile("mma.sync.aligned.m16n8k16.row.col.f32.bf16.bf16.f32 "
                 "{%0,%1,%2,%3}, {%4,%5,%6,%7}, {%8,%9}, {%0,%1,%2,%3};"
                 : "+f"(d[0]), "+f"(d[1]), "+f"(d[2]), "+f"(d[3])
                 : "r"(a[0]), "r"(a[1]), "r"(a[2]), "r"(a[3]), "r"(b[0]), "r"(b[1]));
}

// ---------------------------------------------------------------------------
// GEMM1 via mma.sync bf16 hi/lo split (3 passes, single fp32 accumulator).
// CTA tile 128(M) x 128(N), ktile=16(V). 8 warps in 4x2; warp tile 32x64.
// ---------------------------------------------------------------------------
__global__ __launch_bounds__(256, 2)
void gemm1_mma(const float* __restrict__ fx, const float* __restrict__ fy,
               const float* __restrict__ ex, const float* __restrict__ ey)
{
    __shared__ __align__(16) __nv_bfloat16 Ah[128 * 24], Al[128 * 24];   // stride 48B
    __shared__ __align__(16) __nv_bfloat16 Bh[16 * 136], Bl[16 * 136];   // stride 272B

    const int chunk = blockIdx.x, ntile = blockIdx.y, p = blockIdx.z;
    const int b = p >> 1, which = p & 1;
    const float* E = (which ? ey : ex) + (size_t)b * K_ * V_;
    const float* F = (which ? fy : fx) + (size_t)b * V_ * C_ + ntile * 128;
    // scratch layout MUST be which-major to match reduceA/gemm2: slot = which*4 + b
    float* out = g_part1 + ((size_t)chunk * 8 + which * 4 + b) * K_ * C_ + ntile * 128;

    const int tid = threadIdx.x, wid = tid >> 5, lane = tid & 31;
    const int wm = (wid >> 1) * 32, wn = (wid & 1) * 64;

    const int ar = tid >> 1, ahalf = tid & 1;          // A stage: row, v-half
    const int fv = tid >> 4, fc = (tid & 15) * 8;      // B stage

    const unsigned aAh = smem_u32(Ah), aAl = smem_u32(Al);
    const unsigned aBh = smem_u32(Bh), aBl = smem_u32(Bl);

    float acc[2][8][4];
#pragma unroll
    for (int mt = 0; mt < 2; ++mt)
#pragma unroll
        for (int nt = 0; nt < 8; ++nt)
#pragma unroll
            for (int e = 0; e < 4; ++e) acc[mt][nt][e] = 0.0f;

    const unsigned aoffH0 = aAh + (wm + (lane & 15)) * 48 + (lane >> 4) * 16;
    const unsigned aoffL0 = aAl + (wm + (lane & 15)) * 48 + (lane >> 4) * 16;
    const unsigned brow = (lane & 15);

    const int t0 = chunk * TPC;
    const int t1 = (t0 + TPC < NTILES) ? (t0 + TPC) : NTILES;

    for (int t = t0; t < t1; ++t) {
        const int vb = t << 4;
        const float* Ep = E + (size_t)ar * V_ + vb + ahalf * 8;
        const float* Fp = F + (size_t)(vb + fv) * C_ + fc;
        float4 e0 = *(const float4*)(Ep);
        float4 e1 = *(const float4*)(Ep + 4);
        float4 f0 = *(const float4*)(Fp);
        float4 f1 = *(const float4*)(Fp + 4);
        __syncthreads();
        {
            unsigned h[4], l[4];
            cvt2(e0.x, e0.y, h[0], l[0]); cvt2(e0.z, e0.w, h[1], l[1]);
            cvt2(e1.x, e1.y, h[2], l[2]); cvt2(e1.z, e1.w, h[3], l[3]);
            *(uint4*)((char*)Ah + ar * 48 + ahalf * 16) = make_uint4(h[0], h[1], h[2], h[3]);
            *(uint4*)((char*)Al + ar * 48 + ahalf * 16) = make_uint4(l[0], l[1], l[2], l[3]);
            cvt2(f0.x, f0.y, h[0], l[0]); cvt2(f0.z, f0.w, h[1], l[1]);
            cvt2(f1.x, f1.y, h[2], l[2]); cvt2(f1.z, f1.w, h[3], l[3]);
            *(uint4*)((char*)Bh + fv * 272 + fc * 2) = make_uint4(h[0], h[1], h[2], h[3]);
            *(uint4*)((char*)Bl + fv * 272 + fc * 2) = make_uint4(l[0], l[1], l[2], l[3]);
        }
        __syncthreads();

        unsigned ahf[2][4], alf[2][4];
        ldx4(ahf[0], aoffH0);
        ldx4(ahf[1], aoffH0 + 16 * 48);
        ldx4(alf[0], aoffL0);
        ldx4(alf[1], aoffL0 + 16 * 48);
#pragma unroll
        for (int nt = 0; nt < 8; ++nt) {
            const unsigned boff = brow * 272 + (wn + nt * 8) * 2;
            unsigned bh[2], bl[2];
            ldx2t(bh, aBh + boff);
            ldx2t(bl, aBl + boff);
#pragma unroll
            for (int mt = 0; mt < 2; ++mt) {
                mma16816(acc[mt][nt], ahf[mt], bh);
                mma16816(acc[mt][nt], ahf[mt], bl);
                mma16816(acc[mt][nt], alf[mt], bh);
            }
        }
    }

#pragma unroll
    for (int mt = 0; mt < 2; ++mt)
#pragma unroll
        for (int nt = 0; nt < 8; ++nt) {
            const int row = wm + mt * 16 + (lane >> 2);
            const int col = wn + nt * 8 + (lane & 3) * 2;
            *(float2*)(out + (size_t)row * C_ + col) =
                make_float2(acc[mt][nt][0], acc[mt][nt][1]);
            *(float2*)(out + (size_t)(row + 8) * C_ + col) =
                make_float2(acc[mt][nt][2], acc[mt][nt][3]);
        }
}

__global__ void reduceA()
{
    const int i = blockIdx.x * 256 + threadIdx.x;
    float s = 0.0f;
#pragma unroll
    for (int c = 0; c < NCHUNK; ++c) s += g_part1[(size_t)c * 8 * K_ * C_ + i];
    g_A[i] = s;
}

__global__ __launch_bounds__(256, 2)
void gemm2()
{
    const int cc = blockIdx.x;
    const int t = blockIdx.y & 1, b = blockIdx.y >> 1;
    const float* P = g_A + ((size_t)(t * B_ + b) * K_) * C_ + cc * 128;
    const float* Q = g_A + ((size_t)b * K_) * C_ + cc * 128;
    float* out = g_AA2 + ((size_t)((cc * 2 + t) * B_ + b) * K_) * K_;

    __shared__ float Ps[16][132];
    __shared__ float Qs[16][132];
    const int tid = threadIdx.x;
    const int lk = tid >> 1, lq = tid & 1;
    const int tm = tid >> 4, tn = tid & 15;

    float acc[8][8];
#pragma unroll
    for (int i = 0; i < 8; ++i)
#pragma unroll
        for (int j = 0; j < 8; ++j) acc[i][j] = 0.0f;

    for (int kt = 0; kt < 8; ++kt) {
        const int c = kt << 4;
        float4 p0 = *(const float4*)(P + (size_t)lk * C_ + c + (lq << 2));
        float4 p1 = *(const float4*)(P + (size_t)lk * C_ + c + (lq << 2) + 8);
        float4 q0 = *(const float4*)(Q + (size_t)lk * C_ + c + (lq << 2));
        float4 q1 = *(const float4*)(Q + (size_t)lk * C_ + c + (lq << 2) + 8);
        __syncthreads();
        const int r0 = lq << 2;
        Ps[r0 + 0][lk] = p0.x; Ps[r0 + 1][lk] = p0.y; Ps[r0 + 2][lk] = p0.z; Ps[r0 + 3][lk] = p0.w;
        Ps[r0 + 8][lk] = p1.x; Ps[r0 + 9][lk] = p1.y; Ps[r0 + 10][lk] = p1.z; Ps[r0 + 11][lk] = p1.w;
        Qs[r0 + 0][lk] = q0.x; Qs[r0 + 1][lk] = q0.y; Qs[r0 + 2][lk] = q0.z; Qs[r0 + 3][lk] = q0.w;
        Qs[r0 + 8][lk] = q1.x; Qs[r0 + 9][lk] = q1.y; Qs[r0 + 10][lk] = q1.z; Qs[r0 + 11][lk] = q1.w;
        __syncthreads();
#pragma unroll
        for (int vv = 0; vv < 16; ++vv) {
            float4 a0 = *(const float4*)&Ps[vv][tm << 2];
            float4 a1 = *(const float4*)&Ps[vv][64 + (tm << 2)];
            float4 b0 = *(const float4*)&Qs[vv][tn << 2];
            float4 b1 = *(const float4*)&Qs[vv][64 + (tn << 2)];
            float a[8] = {a0.x, a0.y, a0.z, a0.w, a1.x, a1.y, a1.z, a1.w};
            float bb[8] = {b0.x, b0.y, b0.z, b0.w, b1.x, b1.y, b1.z, b1.w};
#pragma unroll
            for (int i = 0; i < 8; ++i)
#pragma unroll
                for (int j = 0; j < 8; ++j) acc[i][j] += a[i] * bb[j];
        }
    }
#pragma unroll
    for (int i = 0; i < 8; ++i) {
        const int row = (i < 4) ? ((tm << 2) + i) : (64 + (tm << 2) + i - 4);
        float4 o0 = {acc[i][0], acc[i][1], acc[i][2], acc[i][3]};
        float4 o1 = {acc[i][4], acc[i][5], acc[i][6], acc[i][7]};
        *(float4*)(out + (size_t)row * K_ + (tn << 2)) = o0;
        *(float4*)(out + (size_t)row * K_ + 64 + (tn << 2)) = o1;
    }
}

__global__ __launch_bounds__(256, 1)
void factor()
{
    __shared__ float M[K_ * LDI];
    __shared__ float Wd[96 * 33];
    __shared__ float sinvd[K_];
    const int b = blockIdx.x, tid = threadIdx.x;

    const float* X0 = g_AA2 + ((size_t)(0 * B_ + b) * K_) * K_;
    const float* X1 = g_AA2 + ((size_t)(2 * B_ + b) * K_) * K_;
    for (int idx = tid; idx < K_ * K_; idx += 256) {
        const int m = idx >> 7, c = idx & 127;
        M[m * LDI + c] = X0[idx] + X1[idx];
    }
    __syncthreads();

#pragma unroll
    for (int kb = 0; kb < 4; ++kb) {
        const int j0 = kb << 5;
        if (tid < 32) {
            for (int j = 0; j < 32; ++j) {
                const float inv = __frcp_rn(M[(j0 + j) * LDI + j0 + j]);
                if (tid > j) {
                    const float cf = M[(j0 + tid) * LDI + j0 + j] * inv;
                    for (int l = j + 1; l <= tid; ++l)
                        M[(j0 + tid) * LDI + j0 + l] -= cf * M[(j0 + l) * LDI + j0 + j];
                }
                __syncwarp();
            }
            sinvd[j0 + tid] = __frcp_rn(M[(j0 + tid) * LDI + j0 + tid]);
        }
        __syncthreads();

        const int nrows = 96 - (kb << 5);
        if (nrows > 0) {
            if (tid < nrows) {
                const int i = j0 + 32 + tid;
                float w[32];
#pragma unroll
                for (int l = 0; l < 32; ++l) w[l] = M[i * LDI + j0 + l];
#pragma unroll
                for (int l = 0; l < 32; ++l) {
                    const float c = w[l] * sinvd[j0 + l];
#pragma unroll
                    for (int j = l + 1; j < 32; ++j)
                        w[j] -= c * M[(j0 + j) * LDI + j0 + l];
                }
#pragma unroll
                for (int l = 0; l < 32; ++l) {
                    M[i * LDI + j0 + l] = w[l] * sinvd[j0 + l];
                    Wd[tid * 33 + l] = w[l];
                }
            }
            __syncthreads();

            const int total = nrows * nrows;
            for (int e = tid; e < total; e += 256) {
                const int ri = e / nrows, ci = e % nrows;
                if (ci <= ri) {
                    const int i = j0 + 32 + ri, c = j0 + 32 + ci;
                    float s = 0.0f;
#pragma unroll
                    for (int l = 0; l < 32; ++l)
                        s += M[i * LDI + j0 + l] * Wd[ci * 33 + l];
                    M[i * LDI + c] -= s;
                }
            }
            __syncthreads();
        }
    }

    float* Lc = g_Lc + (size_t)b * K_ * K_;
    for (int idx = tid; idx < K_ * K_; idx += 256) {
        const int j = idx >> 7, r = idx & 127;
        float v;
        if (r < j)       v = 0.0f;
        else if (r == j) v = 1.0f;
        else if ((r >> 5) == (j >> 5)) v = M[r * LDI + j] * sinvd[j];
        else             v = M[r * LDI + j];
        Lc[idx] = v;
    }
    if (tid < K_) g_invd[b * K_ + tid] = sinvd[tid];
}

__global__ __launch_bounds__(128)
void bigsolve(const float* __restrict__ evx, const float* __restrict__ evy,
              float* __restrict__ outp)
{
    extern __shared__ float Ls[];
    __shared__ float sinvd[K_];

    const int b = blockIdx.x >> 5, grp = blockIdx.x & 31;
    const int tid = threadIdx.x, w = tid >> 5, k = tid & 31;
    const int i = grp * 4 + w;

    const float* Lc = g_Lc + (size_t)b * K_ * K_;
    for (int idx = tid; idx < K_ * K_; idx += 128) {
        const int j = idx >> 7, t = idx & 127;
        Ls[j * LDI + t] = Lc[idx];
    }
    if (tid < K_) sinvd[tid] = g_invd[b * K_ + tid];

    float r[4], d[4], x[4], invd_r[4];
    const float s = fmaxf(evx[b * K_ + K_ - 1], evy[b * K_ + K_ - 1]);
    const float g2 = sqrtf(evy[b * K_ + i] / s);
    const float h2 = 1.0f / (g2 * g2 + 1.0f);
    const float ya = g2 * h2, yb = h2;
    const float* Y0 = g_AA2 + ((size_t)(1 * B_ + b) * K_ + i) * K_;
    const float* Y1 = g_AA2 + ((size_t)(3 * B_ + b) * K_ + i) * K_;
#pragma unroll
    for (int m = 0; m < 4; ++m) {
        const int t = k + 32 * m;
        r[m] = Y0[t] + Y1[t];
        const float g1 = sqrtf(evx[b * K_ + t] / s);
        const float h1 = 1.0f / (g1 * g1 + 1.0f);
        const float re = ya - g1 * h1, im = yb - h1;
        d[m] = LAMBDA * (re * re + im * im);
        x[m] = 0.0f;
    }
    __syncthreads();
#pragma unroll
    for (int m = 0; m < 4; ++m) invd_r[m] = sinvd[k + 32 * m];

    for (int it = 0; it < 3; ++it) {
        float y[4];
#pragma unroll
        for (int m = 0; m < 4; ++m) y[m] = r[m] - d[m] * x[m];
#pragma unroll
        for (int q = 0; q < 4; ++q)
            for (int j2 = 0; j2 < 32; ++j2) {
                const int j = q * 32 + j2;
                const float yj = __shfl_sync(0xFFFFFFFFu, y[q], j2);
#pragma unroll
                for (int m = 0; m < 4; ++m)
                    if (m > q || (m == q && k > j2))
                        y[m] -= Ls[j * LDI + k + 32 * m] * yj;
            }
#pragma unroll
        for (int m = 0; m < 4; ++m) y[m] *= invd_r[m];
#pragma unroll
        for (int q = 3; q >= 0; --q)
            for (int j2 = 31; j2 >= 0; --j2) {
                const int j = q * 32 + j2;
                const float yj = __shfl_sync(0xFFFFFFFFu, y[q], j2);
#pragma unroll
                for (int m = 0; m < 4; ++m)
                    if (m < q || (m == q && k < j2))
                        y[m] -= Ls[(k + 32 * m) * LDI + j] * yj;
            }
#pragma unroll
        for (int m = 0; m < 4; ++m) x[m] = y[m];
    }
    float* o = outp + ((size_t)(b * K_ + i)) * K_;
#pragma unroll
    for (int m = 0; m < 4; ++m) o[k + 32 * m] = x[m];
}

extern "C" void kernel_launch(void* const* d_in, const int* in_sizes, int n_in,
                              void* d_out, int out_size)
{
    const float* fx  = (const float*)d_in[0];
    const float* fy  = (const float*)d_in[1];
    const float* evx = (const float*)d_in[2];
    const float* evy = (const float*)d_in[3];
    const float* ex  = (const float*)d_in[4];
    const float* ey  = (const float*)d_in[5];
    float* out = (float*)d_out;

    static int attr_done = 0;
    if (!attr_done) {
        cudaFuncSetAttribute(bigsolve, cudaFuncAttributeMaxDynamicSharedMemorySize,
                             K_ * LDI * (int)sizeof(float));
        attr_done = 1;
    }

    gemm1_mma<<<dim3(NCHUNK, 2, 8), 256>>>(fx, fy, ex, ey);
    reduceA<<<(8 * K_ * C_) / 256, 256>>>();
    gemm2<<<dim3(2, 8), 256>>>();
    factor<<<B_, 256>>>();
    bigsolve<<<B_ * 32, 128, K_ * LDI * sizeof(float)>>>(evx, evy, out);
}

// round 11
// speedup vs baseline: 2.6755x; 1.1236x over previous
#include <cuda_runtime.h>
#include <cuda_bf16.h>
#include <math.h>

#define B_ 4
#define V_ 50000
#define C_ 256
#define K_ 128
#define LAMBDA 100.0f
#define NCHUNK 19
#define TPC 165
#define NTILES 3125
#define LDI 129

__device__ float g_part1[(size_t)NCHUNK * 8 * K_ * C_];
__device__ float g_A[8 * K_ * C_];
__device__ float g_AA2[2 * 2 * B_ * K_ * K_];
__device__ float g_Lc[B_ * K_ * K_];
__device__ float g_invd[B_ * K_];

__device__ __forceinline__ unsigned smem_u32(const void* p) {
    unsigned a;
    asm("{ .reg .u64 t; cvta.to.shared.u64 t, %1; cvt.u32.u64 %0, t; }" : "=r"(a) : "l"(p));
    return a;
}
__device__ __forceinline__ void cvt2(float x, float y, unsigned& hi, unsigned& lo) {
    __nv_bfloat162 h = __floats2bfloat162_rn(x, y);
    __nv_bfloat162 l = __floats2bfloat162_rn(x - __bfloat162float(h.x),
                                             y - __bfloat162float(h.y));
    hi = *(unsigned*)&h;
    lo = *(unsigned*)&l;
}
__device__ __forceinline__ void ldx4(unsigned* r, unsigned a) {
    asm volatile("ldmatrix.sync.aligned.m8n8.x4.shared.b16 {%0,%1,%2,%3}, [%4];"
                 : "=r"(r[0]), "=r"(r[1]), "=r"(r[2]), "=r"(r[3]) : "r"(a));
}
__device__ __forceinline__ void ldx2t(unsigned* r, unsigned a) {
    asm volatile("ldmatrix.sync.aligned.m8n8.x2.trans.shared.b16 {%0,%1}, [%2];"
                 : "=r"(r[0]), "=r"(r[1]) : "r"(a));
}
__device__ __forceinline__ void mma16816(float* d, const unsigned* a, const unsigned* b) {
    asm volatile("mma.sync.aligned.m16n8k16.row.col.f32.bf16.bf16.f32 "
                 "{%0,%1,%2,%3}, {%4,%5,%6,%7}, {%8,%9}, {%0,%1,%2,%3};"
                 : "+f"(d[0]), "+f"(d[1]), "+f"(d[2]), "+f"(d[3])
                 : "r"(a[0]), "r"(a[1]), "r"(a[2]), "r"(a[3]), "r"(b[0]), "r"(b[1]));
}

// ---------------------------------------------------------------------------
// GEMM1 via mma.sync bf16 hi/lo split (3 passes, single fp32 accumulator),
// software-pipelined: tile t+1's LDG issues before tile t's MMA.
// ---------------------------------------------------------------------------
__global__ __launch_bounds__(256, 2)
void gemm1_mma(const float* __restrict__ fx, const float* __restrict__ fy,
               const float* __restrict__ ex, const float* __restrict__ ey)
{
    __shared__ __align__(16) __nv_bfloat16 Ah[128 * 24], Al[128 * 24];   // stride 48B
    __shared__ __align__(16) __nv_bfloat16 Bh[16 * 136], Bl[16 * 136];   // stride 272B

    const int chunk = blockIdx.x, ntile = blockIdx.y, p = blockIdx.z;
    const int b = p >> 1, which = p & 1;
    const float* E = (which ? ey : ex) + (size_t)b * K_ * V_;
    const float* F = (which ? fy : fx) + (size_t)b * V_ * C_ + ntile * 128;
    float* out = g_part1 + ((size_t)chunk * 8 + which * 4 + b) * K_ * C_ + ntile * 128;

    const int tid = threadIdx.x, wid = tid >> 5, lane = tid & 31;
    const int wm = (wid >> 1) * 32, wn = (wid & 1) * 64;

    const int ar = tid >> 1, ahalf = tid & 1;
    const int fv = tid >> 4, fc = (tid & 15) * 8;

    const unsigned aAh = smem_u32(Ah), aAl = smem_u32(Al);
    const unsigned aBh = smem_u32(Bh), aBl = smem_u32(Bl);

    float acc[2][8][4];
#pragma unroll
    for (int mt = 0; mt < 2; ++mt)
#pragma unroll
        for (int nt = 0; nt < 8; ++nt)
#pragma unroll
            for (int e = 0; e < 4; ++e) acc[mt][nt][e] = 0.0f;

    const unsigned aoffH0 = aAh + (wm + (lane & 15)) * 48 + (lane >> 4) * 16;
    const unsigned aoffL0 = aAl + (wm + (lane & 15)) * 48 + (lane >> 4) * 16;
    const unsigned brow = (lane & 15);

    const int t0 = chunk * TPC;
    const int t1 = (t0 + TPC < NTILES) ? (t0 + TPC) : NTILES;

    const float* Ebase = E + (size_t)ar * V_ + ahalf * 8;

    float4 e0, e1, f0, f1;
    {
        const int vb = t0 << 4;
        e0 = *(const float4*)(Ebase + vb);
        e1 = *(const float4*)(Ebase + vb + 4);
        const float* Fp = F + (size_t)(vb + fv) * C_ + fc;
        f0 = *(const float4*)(Fp);
        f1 = *(const float4*)(Fp + 4);
    }

    for (int t = t0; t < t1; ++t) {
        __syncthreads();
        {
            unsigned h[4], l[4];
            cvt2(e0.x, e0.y, h[0], l[0]); cvt2(e0.z, e0.w, h[1], l[1]);
            cvt2(e1.x, e1.y, h[2], l[2]); cvt2(e1.z, e1.w, h[3], l[3]);
            *(uint4*)((char*)Ah + ar * 48 + ahalf * 16) = make_uint4(h[0], h[1], h[2], h[3]);
            *(uint4*)((char*)Al + ar * 48 + ahalf * 16) = make_uint4(l[0], l[1], l[2], l[3]);
            cvt2(f0.x, f0.y, h[0], l[0]); cvt2(f0.z, f0.w, h[1], l[1]);
            cvt2(f1.x, f1.y, h[2], l[2]); cvt2(f1.z, f1.w, h[3], l[3]);
            *(uint4*)((char*)Bh + fv * 272 + fc * 2) = make_uint4(h[0], h[1], h[2], h[3]);
            *(uint4*)((char*)Bl + fv * 272 + fc * 2) = make_uint4(l[0], l[1], l[2], l[3]);
        }
        __syncthreads();

        // prefetch next tile's globals (latency hidden under the MMAs below)
        if (t + 1 < t1) {
            const int vb = (t + 1) << 4;
            e0 = *(const float4*)(Ebase + vb);
            e1 = *(const float4*)(Ebase + vb + 4);
            const float* Fp = F + (size_t)(vb + fv) * C_ + fc;
            f0 = *(const float4*)(Fp);
            f1 = *(const float4*)(Fp + 4);
        }

        unsigned ahf[2][4], alf[2][4];
        ldx4(ahf[0], aoffH0);
        ldx4(ahf[1], aoffH0 + 16 * 48);
        ldx4(alf[0], aoffL0);
        ldx4(alf[1], aoffL0 + 16 * 48);
#pragma unroll
        for (int nt = 0; nt < 8; ++nt) {
            const unsigned boff = brow * 272 + (wn + nt * 8) * 2;
            unsigned bh[2], bl[2];
            ldx2t(bh, aBh + boff);
            ldx2t(bl, aBl + boff);
#pragma unroll
            for (int mt = 0; mt < 2; ++mt) {
                mma16816(acc[mt][nt], ahf[mt], bh);
                mma16816(acc[mt][nt], ahf[mt], bl);
                mma16816(acc[mt][nt], alf[mt], bh);
            }
        }
    }

#pragma unroll
    for (int mt = 0; mt < 2; ++mt)
#pragma unroll
        for (int nt = 0; nt < 8; ++nt) {
            const int row = wm + mt * 16 + (lane >> 2);
            const int col = wn + nt * 8 + (lane & 3) * 2;
            *(float2*)(out + (size_t)row * C_ + col) =
                make_float2(acc[mt][nt][0], acc[mt][nt][1]);
            *(float2*)(out + (size_t)(row + 8) * C_ + col) =
                make_float2(acc[mt][nt][2], acc[mt][nt][3]);
        }
}

__global__ void reduceA()
{
    const int i = blockIdx.x * 256 + threadIdx.x;
    float s = 0.0f;
#pragma unroll
    for (int c = 0; c < NCHUNK; ++c) s += g_part1[(size_t)c * 8 * K_ * C_ + i];
    g_A[i] = s;
}

__global__ __launch_bounds__(256, 2)
void gemm2()
{
    const int cc = blockIdx.x;
    const int t = blockIdx.y & 1, b = blockIdx.y >> 1;
    const float* P = g_A + ((size_t)(t * B_ + b) * K_) * C_ + cc * 128;
    const float* Q = g_A + ((size_t)b * K_) * C_ + cc * 128;
    float* out = g_AA2 + ((size_t)((cc * 2 + t) * B_ + b) * K_) * K_;

    __shared__ float Ps[16][132];
    __shared__ float Qs[16][132];
    const int tid = threadIdx.x;
    const int lk = tid >> 1, lq = tid & 1;
    const int tm = tid >> 4, tn = tid & 15;

    float acc[8][8];
#pragma unroll
    for (int i = 0; i < 8; ++i)
#pragma unroll
        for (int j = 0; j < 8; ++j) acc[i][j] = 0.0f;

    for (int kt = 0; kt < 8; ++kt) {
        const int c = kt << 4;
        float4 p0 = *(const float4*)(P + (size_t)lk * C_ + c + (lq << 2));
        float4 p1 = *(const float4*)(P + (size_t)lk * C_ + c + (lq << 2) + 8);
        float4 q0 = *(const float4*)(Q + (size_t)lk * C_ + c + (lq << 2));
        float4 q1 = *(const float4*)(Q + (size_t)lk * C_ + c + (lq << 2) + 8);
        __syncthreads();
        const int r0 = lq << 2;
        Ps[r0 + 0][lk] = p0.x; Ps[r0 + 1][lk] = p0.y; Ps[r0 + 2][lk] = p0.z; Ps[r0 + 3][lk] = p0.w;
        Ps[r0 + 8][lk] = p1.x; Ps[r0 + 9][lk] = p1.y; Ps[r0 + 10][lk] = p1.z; Ps[r0 + 11][lk] = p1.w;
        Qs[r0 + 0][lk] = q0.x; Qs[r0 + 1][lk] = q0.y; Qs[r0 + 2][lk] = q0.z; Qs[r0 + 3][lk] = q0.w;
        Qs[r0 + 8][lk] = q1.x; Qs[r0 + 9][lk] = q1.y; Qs[r0 + 10][lk] = q1.z; Qs[r0 + 11][lk] = q1.w;
        __syncthreads();
#pragma unroll
        for (int vv = 0; vv < 16; ++vv) {
            float4 a0 = *(const float4*)&Ps[vv][tm << 2];
            float4 a1 = *(const float4*)&Ps[vv][64 + (tm << 2)];
            float4 b0 = *(const float4*)&Qs[vv][tn << 2];
            float4 b1 = *(const float4*)&Qs[vv][64 + (tn << 2)];
            float a[8] = {a0.x, a0.y, a0.z, a0.w, a1.x, a1.y, a1.z, a1.w};
            float bb[8] = {b0.x, b0.y, b0.z, b0.w, b1.x, b1.y, b1.z, b1.w};
#pragma unroll
            for (int i = 0; i < 8; ++i)
#pragma unroll
                for (int j = 0; j < 8; ++j) acc[i][j] += a[i] * bb[j];
        }
    }
#pragma unroll
    for (int i = 0; i < 8; ++i) {
        const int row = (i < 4) ? ((tm << 2) + i) : (64 + (tm << 2) + i - 4);
        float4 o0 = {acc[i][0], acc[i][1], acc[i][2], acc[i][3]};
        float4 o1 = {acc[i][4], acc[i][5], acc[i][6], acc[i][7]};
        *(float4*)(out + (size_t)row * K_ + (tn << 2)) = o0;
        *(float4*)(out + (size_t)row * K_ + 64 + (tn << 2)) = o1;
    }
}

__global__ __launch_bounds__(256, 1)
void factor()
{
    __shared__ float M[K_ * LDI];
    __shared__ float Wd[96 * 33];
    __shared__ float sinvd[K_];
    const int b = blockIdx.x, tid = threadIdx.x;

    const float* X0 = g_AA2 + ((size_t)(0 * B_ + b) * K_) * K_;
    const float* X1 = g_AA2 + ((size_t)(2 * B_ + b) * K_) * K_;
    for (int idx = tid; idx < K_ * K_; idx += 256) {
        const int m = idx >> 7, c = idx & 127;
        M[m * LDI + c] = X0[idx] + X1[idx];
    }
    __syncthreads();

#pragma unroll
    for (int kb = 0; kb < 4; ++kb) {
        const int j0 = kb << 5;
        if (tid < 32) {
            for (int j = 0; j < 32; ++j) {
                const float inv = __frcp_rn(M[(j0 + j) * LDI + j0 + j]);
                if (tid > j) {
                    const float cf = M[(j0 + tid) * LDI + j0 + j] * inv;
                    for (int l = j + 1; l <= tid; ++l)
                        M[(j0 + tid) * LDI + j0 + l] -= cf * M[(j0 + l) * LDI + j0 + j];
                }
                __syncwarp();
            }
            sinvd[j0 + tid] = __frcp_rn(M[(j0 + tid) * LDI + j0 + tid]);
        }
        __syncthreads();

        const int nrows = 96 - (kb << 5);
        if (nrows > 0) {
            if (tid < nrows) {
                const int i = j0 + 32 + tid;
                float w[32];
#pragma unroll
                for (int l = 0; l < 32; ++l) w[l] = M[i * LDI + j0 + l];
#pragma unroll
                for (int l = 0; l < 32; ++l) {
                    const float c = w[l] * sinvd[j0 + l];
#pragma unroll
                    for (int j = l + 1; j < 32; ++j)
                        w[j] -= c * M[(j0 + j) * LDI + j0 + l];
                }
#pragma unroll
                for (int l = 0; l < 32; ++l) {
                    M[i * LDI + j0 + l] = w[l] * sinvd[j0 + l];
                    Wd[tid * 33 + l] = w[l];
                }
            }
            __syncthreads();

            // trailing update, 2x2 register-blocked (lower-triangle blocks only;
            // stray upper-element writes are never read downstream)
            const int nb = nrows >> 1;
            for (int e = tid; e < nb * nb; e += 256) {
                const int rb = e / nb, cb = e % nb;
                if (cb <= rb) {
                    const int i0 = j0 + 32 + rb * 2, c0 = j0 + 32 + cb * 2;
                    float s00 = 0.f, s01 = 0.f, s10 = 0.f, s11 = 0.f;
#pragma unroll
                    for (int l = 0; l < 32; ++l) {
                        const float m0 = M[i0 * LDI + j0 + l];
                        const float m1 = M[(i0 + 1) * LDI + j0 + l];
                        const float w0 = Wd[(cb * 2) * 33 + l];
                        const float w1 = Wd[(cb * 2 + 1) * 33 + l];
                        s00 += m0 * w0; s01 += m0 * w1;
                        s10 += m1 * w0; s11 += m1 * w1;
                    }
                    M[i0 * LDI + c0]           -= s00;
                    M[i0 * LDI + c0 + 1]       -= s01;
                    M[(i0 + 1) * LDI + c0]     -= s10;
                    M[(i0 + 1) * LDI + c0 + 1] -= s11;
                }
            }
            __syncthreads();
        }
    }

    float* Lc = g_Lc + (size_t)b * K_ * K_;
    for (int idx = tid; idx < K_ * K_; idx += 256) {
        const int j = idx >> 7, r = idx & 127;
        float v;
        if (r < j)       v = 0.0f;
        else if (r == j) v = 1.0f;
        else if ((r >> 5) == (j >> 5)) v = M[r * LDI + j] * sinvd[j];
        else             v = M[r * LDI + j];
        Lc[idx] = v;
    }
    if (tid < K_) g_invd[b * K_ + tid] = sinvd[tid];
}

__global__ __launch_bounds__(128)
void bigsolve(const float* __restrict__ evx, const float* __restrict__ evy,
              float* __restrict__ outp)
{
    extern __shared__ float Ls[];
    __shared__ float sinvd[K_];

    const int b = blockIdx.x >> 5, grp = blockIdx.x & 31;
    const int tid = threadIdx.x, w = tid >> 5, k = tid & 31;
    const int i = grp * 4 + w;

    const float* Lc = g_Lc + (size_t)b * K_ * K_;
    for (int idx = tid; idx < K_ * K_; idx += 128) {
        const int j = idx >> 7, t = idx & 127;
        Ls[j * LDI + t] = Lc[idx];
    }
    if (tid < K_) sinvd[tid] = g_invd[b * K_ + tid];

    float r[4], d[4], x[4], invd_r[4];
    const float s = fmaxf(evx[b * K_ + K_ - 1], evy[b * K_ + K_ - 1]);
    const float g2 = sqrtf(evy[b * K_ + i] / s);
    const float h2 = 1.0f / (g2 * g2 + 1.0f);
    const float ya = g2 * h2, yb = h2;
    const float* Y0 = g_AA2 + ((size_t)(1 * B_ + b) * K_ + i) * K_;
    const float* Y1 = g_AA2 + ((size_t)(3 * B_ + b) * K_ + i) * K_;
#pragma unroll
    for (int m = 0; m < 4; ++m) {
        const int t = k + 32 * m;
        r[m] = Y0[t] + Y1[t];
        const float g1 = sqrtf(evx[b * K_ + t] / s);
        const float h1 = 1.0f / (g1 * g1 + 1.0f);
        const float re = ya - g1 * h1, im = yb - h1;
        d[m] = LAMBDA * (re * re + im * im);
        x[m] = 0.0f;
    }
    __syncthreads();
#pragma unroll
    for (int m = 0; m < 4; ++m) invd_r[m] = sinvd[k + 32 * m];

    for (int it = 0; it < 3; ++it) {
        float y[4];
#pragma unroll
        for (int m = 0; m < 4; ++m) y[m] = r[m] - d[m] * x[m];
#pragma unroll
        for (int q = 0; q < 4; ++q)
            for (int j2 = 0; j2 < 32; ++j2) {
                const int j = q * 32 + j2;
                const float yj = __shfl_sync(0xFFFFFFFFu, y[q], j2);
#pragma unroll
                for (int m = 0; m < 4; ++m)
                    if (m > q || (m == q && k > j2))
                        y[m] -= Ls[j * LDI + k + 32 * m] * yj;
            }
#pragma unroll
        for (int m = 0; m < 4; ++m) y[m] *= invd_r[m];
#pragma unroll
        for (int q = 3; q >= 0; --q)
            for (int j2 = 31; j2 >= 0; --j2) {
                const int j = q * 32 + j2;
                const float yj = __shfl_sync(0xFFFFFFFFu, y[q], j2);
#pragma unroll
                for (int m = 0; m < 4; ++m)
                    if (m < q || (m == q && k < j2))
                        y[m] -= Ls[(k + 32 * m) * LDI + j] * yj;
            }
#pragma unroll
        for (int m = 0; m < 4; ++m) x[m] = y[m];
    }
    float* o = outp + ((size_t)(b * K_ + i)) * K_;
#pragma unroll
    for (int m = 0; m < 4; ++m) o[k + 32 * m] = x[m];
}

extern "C" void kernel_launch(void* const* d_in, const int* in_sizes, int n_in,
                              void* d_out, int out_size)
{
    const float* fx  = (const float*)d_in[0];
    const float* fy  = (const float*)d_in[1];
    const float* evx = (const float*)d_in[2];
    const float* evy = (const float*)d_in[3];
    const float* ex  = (const float*)d_in[4];
    const float* ey  = (const float*)d_in[5];
    float* out = (float*)d_out;

    static int attr_done = 0;
    if (!attr_done) {
        cudaFuncSetAttribute(bigsolve, cudaFuncAttributeMaxDynamicSharedMemorySize,
                             K_ * LDI * (int)sizeof(float));
        attr_done = 1;
    }

    gemm1_mma<<<dim3(NCHUNK, 2, 8), 256>>>(fx, fy, ex, ey);
    reduceA<<<(8 * K_ * C_) / 256, 256>>>();
    gemm2<<<dim3(2, 8), 256>>>();
    factor<<<B_, 256>>>();
    bigsolve<<<B_ * 32, 128, K_ * LDI * sizeof(float)>>>(evx, evy, out);
}